// round 1
// baseline (speedup 1.0000x reference)
#include <cuda_runtime.h>

#define C_   64
#define O_   64
#define H_   128
#define W_   128
#define KK   9
#define HW_  (H_ * W_)

// smem: weights reorganized [k][c][o] (9*64*64 floats) + bias (64 floats)
#define WSM_FLOATS (KK * C_ * O_)
#define SMEM_BYTES ((WSM_FLOATS + O_) * 4)

__global__ __launch_bounds__(256, 1)
void deform_conv_kernel(const float* __restrict__ x,
                        const float* __restrict__ offset,
                        const float* __restrict__ weight,
                        const float* __restrict__ bias,
                        float* __restrict__ out) {
    extern __shared__ float wsm[];
    const int tid = threadIdx.x;

    // Stage weights: global [o][c][k] -> smem [k][c][o]
    // (coalesced global reads; scattered smem writes are one-time cost)
    for (int i = tid; i < O_ * C_ * KK; i += 256) {
        int o   = i / (C_ * KK);
        int rem = i - o * (C_ * KK);
        int c   = rem / KK;
        int k   = rem - c * KK;
        wsm[(k * C_ + c) * O_ + o] = weight[i];
    }
    if (tid < O_) wsm[WSM_FLOATS + tid] = bias[tid];
    __syncthreads();

    // 64 blocks per batch, 256 pixels per block
    const int b  = blockIdx.x >> 6;
    const int px = ((blockIdx.x & 63) << 8) + tid;   // 0..16383
    const int ho = px >> 7;
    const int wo = px & (W_ - 1);

    float acc[O_];
    #pragma unroll
    for (int o = 0; o < O_; o++) acc[o] = 0.f;

    const float* xb   = x + b * C_ * HW_;
    const float* offb = offset + b * (2 * KK) * HW_;

    for (int k = 0; k < KK; k++) {
        const int ki = k / 3;
        const int kj = k - ki * 3;

        // offset channel layout: ch = 2k -> y offset, 2k+1 -> x offset
        const float offy = offb[(2 * k)     * HW_ + px];
        const float offx = offb[(2 * k + 1) * HW_ + px];

        // p = offset + tap*DIL + base (stride=1, pad=1, dil=1)
        const float py  = offy + (float)(ki - 1 + ho);
        const float pxx = offx + (float)(kj - 1 + wo);

        const float y0f = floorf(py);
        const float x0f = floorf(pxx);
        const float ly  = py  - y0f;
        const float lx  = pxx - x0f;
        const float hy  = 1.f - ly;
        const float hx  = 1.f - lx;

        const int y0 = (int)y0f;
        const int x0 = (int)x0f;
        const int y1 = y0 + 1;
        const int x1 = x0 + 1;

        const bool vy0 = (y0 >= 0) && (y0 < H_);
        const bool vy1 = (y1 >= 0) && (y1 < H_);
        const bool vx0 = (x0 >= 0) && (x0 < W_);
        const bool vx1 = (x1 >= 0) && (x1 < W_);

        const int cy0 = min(max(y0, 0), H_ - 1);
        const int cy1 = min(max(y1, 0), H_ - 1);
        const int cx0 = min(max(x0, 0), W_ - 1);
        const int cx1 = min(max(x1, 0), W_ - 1);

        const float w00 = (vy0 && vx0) ? hy * hx : 0.f;
        const float w01 = (vy0 && vx1) ? hy * lx : 0.f;
        const float w10 = (vy1 && vx0) ? ly * hx : 0.f;
        const float w11 = (vy1 && vx1) ? ly * lx : 0.f;

        const int i00 = cy0 * W_ + cx0;
        const int i01 = cy0 * W_ + cx1;
        const int i10 = cy1 * W_ + cx0;
        const int i11 = cy1 * W_ + cx1;

        const float4* wk = reinterpret_cast<const float4*>(wsm + k * C_ * O_);
        const float*  xc = xb;

        for (int c = 0; c < C_; c++) {
            // bilinear sample for channel c (weights already masked)
            const float v = w00 * __ldg(xc + i00) + w01 * __ldg(xc + i01)
                          + w10 * __ldg(xc + i10) + w11 * __ldg(xc + i11);

            // rank-1 update into 64 output-channel accumulators
            const float4* wrow = wk + c * (O_ / 4);
            #pragma unroll
            for (int o4 = 0; o4 < O_ / 4; o4++) {
                const float4 wv = wrow[o4];   // broadcast LDS.128
                acc[o4 * 4 + 0] += v * wv.x;
                acc[o4 * 4 + 1] += v * wv.y;
                acc[o4 * 4 + 2] += v * wv.z;
                acc[o4 * 4 + 3] += v * wv.w;
            }
            xc += HW_;
        }
    }

    // out[b][o][ho][wo]: coalesced per o-plane
    float* ob = out + b * O_ * HW_ + px;
    #pragma unroll
    for (int o = 0; o < O_; o++) {
        ob[o * HW_] = acc[o] + wsm[WSM_FLOATS + o];
    }
}

extern "C" void kernel_launch(void* const* d_in, const int* in_sizes, int n_in,
                              void* d_out, int out_size) {
    const float* x      = (const float*)d_in[0];
    const float* offset = (const float*)d_in[1];
    const float* weight = (const float*)d_in[2];
    const float* bias   = (const float*)d_in[3];
    float* out = (float*)d_out;

    cudaFuncSetAttribute(deform_conv_kernel,
                         cudaFuncAttributeMaxDynamicSharedMemorySize, SMEM_BYTES);

    // 4 batches * 64 blocks = 256 blocks, 256 threads each -> 65536 pixels
    deform_conv_kernel<<<256, 256, SMEM_BYTES>>>(x, offset, weight, bias, out);
}

// round 2
// speedup vs baseline: 1.9011x; 1.9011x over previous
#include <cuda_runtime.h>

#define B_   4
#define C_   64
#define O_   64
#define H_   128
#define W_   128
#define KK   9
#define HW_  (H_ * W_)

// Scratch (allocation-free rule: __device__ globals)
__device__ float2 g_x2[B_ * C_ * HW_];      // paired x: (x[y][x], x[y][x+1])  ~33.5 MB
__device__ float  g_wT[KK * C_ * O_];       // weights transposed to [k][c][o]

// ---------- prep kernels ----------
__global__ void prep_weights(const float* __restrict__ w) {
    int i = blockIdx.x * 256 + threadIdx.x;          // over O*C*KK = 36864
    if (i < O_ * C_ * KK) {
        int o = i / (C_ * KK);
        int r = i - o * (C_ * KK);
        int c = r / KK;
        int k = r - c * KK;
        g_wT[(k * C_ + c) * O_ + o] = w[i];
    }
}

__global__ void prep_x2(const float* __restrict__ x) {
    int i = blockIdx.x * 256 + threadIdx.x;          // over B*C*HW = 4194304
    if (i < B_ * C_ * HW_) {
        int col = i & (W_ - 1);
        float a = x[i];
        float b = (col < W_ - 1) ? x[i + 1] : a;     // clamp; weight is 0 there anyway
        g_x2[i] = make_float2(a, b);
    }
}

// ---------- main kernel ----------
// grid: 512 blocks (batch*128 rows), 128 threads.
// Block computes one output row (128 px) x 64 o-channels.
// smem: vtile[64][128] (sampled values per k-tap) + wslab[64][64] (per-k weights)
#define SMEM_BYTES ((C_ * W_ + C_ * O_) * 4)   // 49152 = 48KB

#define PACK2(d, s)   asm("mov.b64 %0, {%1, %1};" : "=l"(d) : "r"(__float_as_uint(s)))
#define FMA2(a, w, v) asm("fma.rn.f32x2 %0, %1, %2, %0;" : "+l"(a) : "l"(w), "l"(v))
#define UNPK(lo, hi, a) asm("mov.b64 {%0, %1}, %2;" : "=r"(lo), "=r"(hi) : "l"(a))

__global__ __launch_bounds__(128, 4)
void dconv_main(const float* __restrict__ offset,
                const float* __restrict__ bias,
                float* __restrict__ out) {
    extern __shared__ float sm[];
    float* vtile = sm;              // [64][128]
    float* wslab = sm + C_ * W_;    // [64][64]

    const int tid   = threadIdx.x;
    const int batch = blockIdx.x >> 7;
    const int ho    = blockIdx.x & 127;

    const float2* xb2  = g_x2 + batch * C_ * HW_;
    const float*  offb = offset + (batch * 2 * KK) * HW_ + ho * W_ + tid;

    unsigned long long acc[32];     // [px 0..3][o-pair 0..7], packed f32x2
    #pragma unroll
    for (int i = 0; i < 32; i++) acc[i] = 0ULL;

    const int pxq = tid & 31;       // pixel quad: wo = pxq*4 .. pxq*4+3
    const int og  = tid >> 5;       // o-group: o = og*16 .. og*16+15

    for (int k = 0; k < KK; k++) {
        __syncthreads();
        // stage this tap's weight slab [c][o] (coalesced float4)
        {
            const float4* src = (const float4*)(g_wT + k * C_ * O_);
            float4* dst = (float4*)wslab;
            #pragma unroll
            for (int j = 0; j < 8; j++) dst[tid + j * 128] = src[tid + j * 128];
        }
        // sampling phase: thread = pixel (wo = tid); corner math once, 64 channels
        {
            const int ki = k / 3, kj = k - ki * 3;
            const float offy = offb[(2 * k) * HW_];
            const float offx = offb[(2 * k + 1) * HW_];
            const float py  = offy + (float)(ki - 1 + ho);
            const float pxx = offx + (float)(kj - 1 + tid);

            const float y0f = floorf(py), x0f = floorf(pxx);
            const float ly = py - y0f,  lx = pxx - x0f;
            const float hy = 1.f - ly,  hx = 1.f - lx;
            const int y0 = (int)y0f, x0 = (int)x0f;

            const float wy0 = (y0 >= 0  && y0 < H_)     ? hy : 0.f;
            const float wy1 = (y0 >= -1 && y0 < H_ - 1) ? ly : 0.f;
            const int ry0 = min(max(y0, 0), H_ - 1);
            const int ry1 = min(max(y0 + 1, 0), H_ - 1);

            // pair weights with boundary fold: pair at bx holds (x[bx], x[bx+1])
            float wa, wb;
            if (x0 >= 0 && x0 < W_) { wa = hx; wb = (x0 < W_ - 1) ? lx : 0.f; }
            else if (x0 == -1)      { wa = lx; wb = 0.f; }   // pair.x = x[0] = right tap
            else                    { wa = 0.f; wb = 0.f; }
            const int bx = min(max(x0, 0), W_ - 1);

            const float u0 = wy0 * wa, u1 = wy0 * wb;
            const float u2 = wy1 * wa, u3 = wy1 * wb;

            const float2* p0 = xb2 + ry0 * W_ + bx;
            const float2* p1 = xb2 + ry1 * W_ + bx;
            #pragma unroll 4
            for (int c = 0; c < C_; c++) {
                const float2 a = __ldg(p0 + c * HW_);   // one LDG.64 per row-pair
                const float2 b = __ldg(p1 + c * HW_);
                vtile[c * W_ + tid] = u0 * a.x + u1 * a.y + u2 * b.x + u3 * b.y;
            }
        }
        __syncthreads();

        // GEMM phase: 4 px x 16 o per thread, packed f32x2 FMAs
        const float4*     vt = (const float4*)vtile;          // [c][32 quads]
        const ulonglong2* wt = (const ulonglong2*)wslab;      // [c][16 x (2 pairs)]
        #pragma unroll 2
        for (int c = 0; c < C_; c++) {
            const float4 v4 = vt[c * 32 + pxq];
            const ulonglong2* wr = wt + c * 16 + og * 4;
            const ulonglong2 wA = wr[0], wB = wr[1], wC = wr[2], wD = wr[3];

            unsigned long long vv0, vv1, vv2, vv3;
            PACK2(vv0, v4.x); PACK2(vv1, v4.y); PACK2(vv2, v4.z); PACK2(vv3, v4.w);

            FMA2(acc[0],  wA.x, vv0); FMA2(acc[1],  wA.y, vv0);
            FMA2(acc[2],  wB.x, vv0); FMA2(acc[3],  wB.y, vv0);
            FMA2(acc[4],  wC.x, vv0); FMA2(acc[5],  wC.y, vv0);
            FMA2(acc[6],  wD.x, vv0); FMA2(acc[7],  wD.y, vv0);

            FMA2(acc[8],  wA.x, vv1); FMA2(acc[9],  wA.y, vv1);
            FMA2(acc[10], wB.x, vv1); FMA2(acc[11], wB.y, vv1);
            FMA2(acc[12], wC.x, vv1); FMA2(acc[13], wC.y, vv1);
            FMA2(acc[14], wD.x, vv1); FMA2(acc[15], wD.y, vv1);

            FMA2(acc[16], wA.x, vv2); FMA2(acc[17], wA.y, vv2);
            FMA2(acc[18], wB.x, vv2); FMA2(acc[19], wB.y, vv2);
            FMA2(acc[20], wC.x, vv2); FMA2(acc[21], wC.y, vv2);
            FMA2(acc[22], wD.x, vv2); FMA2(acc[23], wD.y, vv2);

            FMA2(acc[24], wA.x, vv3); FMA2(acc[25], wA.y, vv3);
            FMA2(acc[26], wB.x, vv3); FMA2(acc[27], wB.y, vv3);
            FMA2(acc[28], wC.x, vv3); FMA2(acc[29], wC.y, vv3);
            FMA2(acc[30], wD.x, vv3); FMA2(acc[31], wD.y, vv3);
        }
    }

    // epilogue: unpack, add bias, vector stores (4 px contiguous per o)
    float* ob = out + (batch * O_) * HW_ + ho * W_ + pxq * 4;
    #pragma unroll
    for (int pr = 0; pr < 8; pr++) {
        const int o = og * 16 + 2 * pr;
        const float b0 = __ldg(bias + o);
        const float b1 = __ldg(bias + o + 1);
        unsigned int l0, h0, l1, h1, l2, h2, l3, h3;
        UNPK(l0, h0, acc[pr]);
        UNPK(l1, h1, acc[8 + pr]);
        UNPK(l2, h2, acc[16 + pr]);
        UNPK(l3, h3, acc[24 + pr]);
        float4 r0 = make_float4(__uint_as_float(l0) + b0, __uint_as_float(l1) + b0,
                                __uint_as_float(l2) + b0, __uint_as_float(l3) + b0);
        float4 r1 = make_float4(__uint_as_float(h0) + b1, __uint_as_float(h1) + b1,
                                __uint_as_float(h2) + b1, __uint_as_float(h3) + b1);
        *(float4*)(ob + o * HW_)       = r0;
        *(float4*)(ob + (o + 1) * HW_) = r1;
    }
}

extern "C" void kernel_launch(void* const* d_in, const int* in_sizes, int n_in,
                              void* d_out, int out_size) {
    const float* x      = (const float*)d_in[0];
    const float* offset = (const float*)d_in[1];
    const float* weight = (const float*)d_in[2];
    const float* bias   = (const float*)d_in[3];
    float* out = (float*)d_out;

    cudaFuncSetAttribute(dconv_main,
                         cudaFuncAttributeMaxDynamicSharedMemorySize, SMEM_BYTES);

    prep_weights<<<(O_ * C_ * KK + 255) / 256, 256>>>(weight);
    prep_x2<<<(B_ * C_ * HW_ + 255) / 256, 256>>>(x);
    dconv_main<<<B_ * H_, 128, SMEM_BYTES>>>(offset, bias, out);
}

// round 3
// speedup vs baseline: 2.0035x; 1.0539x over previous
#include <cuda_runtime.h>

#define B_   4
#define C_   64
#define O_   64
#define H_   128
#define W_   128
#define KK   9
#define HW_  (H_ * W_)

// Scratch (allocation-free rule: __device__ globals)
__device__ float2 g_x2[B_ * C_ * HW_];      // paired x: (x[y][x], x[y][x+1])
__device__ float  g_wT[KK * C_ * O_];       // weights transposed to [k][c][o]

// ---------- prep kernels ----------
__global__ void prep_weights(const float* __restrict__ w) {
    int i = blockIdx.x * 256 + threadIdx.x;          // over O*C*KK = 36864
    if (i < O_ * C_ * KK) {
        int o = i / (C_ * KK);
        int r = i - o * (C_ * KK);
        int c = r / KK;
        int k = r - c * KK;
        g_wT[(k * C_ + c) * O_ + o] = w[i];
    }
}

__global__ void prep_x2(const float* __restrict__ x) {
    int i = blockIdx.x * 256 + threadIdx.x;          // over B*C*HW = 4194304
    if (i < B_ * C_ * HW_) {
        int col = i & (W_ - 1);
        float a = x[i];
        float b = (col < W_ - 1) ? x[i + 1] : a;     // clamp; weight is 0 there
        g_x2[i] = make_float2(a, b);
    }
}

// ---------- main kernel ----------
// 512 blocks (batch*row), 256 threads: warps 0-3 consume (GEMM), 4-7 produce.
// smem: double-buffered vtile[2][64][128] + wslab[2][64][64]  = 96 KB
#define VT_FLOATS (C_ * W_)
#define WS_FLOATS (C_ * O_)
#define SMEM_BYTES ((2 * VT_FLOATS + 2 * WS_FLOATS) * 4)

#define PACK2(d, s)     asm("mov.b64 %0, {%1, %1};" : "=l"(d) : "r"(__float_as_uint(s)))
#define FMA2(a, w, v)   asm("fma.rn.f32x2 %0, %1, %2, %0;" : "+l"(a) : "l"(w), "l"(v))
#define UNPK(lo, hi, a) asm("mov.b64 {%0, %1}, %2;" : "=r"(lo), "=r"(hi) : "l"(a))

// named barriers: 1+s = "stage s full", 3+s = "stage s empty"; count = 256
#define BSYNC(id)   asm volatile("bar.sync %0, 256;"   :: "r"(id) : "memory")
#define BARRIVE(id) asm volatile("bar.arrive %0, 256;" :: "r"(id) : "memory")

__global__ __launch_bounds__(256, 2)
void dconv_main(const float* __restrict__ offset,
                const float* __restrict__ bias,
                float* __restrict__ out) {
    extern __shared__ float sm[];
    float* vtile = sm;                       // [2][64][128]
    float* wslab = sm + 2 * VT_FLOATS;       // [2][64][64]

    const int tid   = threadIdx.x;
    const int batch = blockIdx.x >> 7;
    const int ho    = blockIdx.x & 127;

    if (tid >= 128) {
        // ================= PRODUCER (warps 4-7) =================
        const int p = tid - 128;             // pixel index 0..127
        const float2* xb2  = g_x2 + batch * C_ * HW_;
        const float*  offb = offset + (batch * 2 * KK) * HW_ + ho * W_ + p;

        // hoist all tap offsets (coalesced)
        float offy[KK], offx[KK];
        #pragma unroll
        for (int k = 0; k < KK; k++) {
            offy[k] = __ldg(offb + (2 * k) * HW_);
            offx[k] = __ldg(offb + (2 * k + 1) * HW_);
        }

        for (int k = 0; k < KK; k++) {
            const int s = k & 1;
            if (k >= 2) BSYNC(3 + s);        // wait stage empty

            // stage weights for tap k (coalesced float4)
            {
                const float4* src = (const float4*)(g_wT + k * WS_FLOATS);
                float4* dst = (float4*)(wslab + s * WS_FLOATS);
                #pragma unroll
                for (int j = 0; j < 8; j++) dst[p + j * 128] = src[p + j * 128];
            }

            // bilinear corner math once per (pixel, tap)
            const int ki = k / 3, kj = k - ki * 3;
            const float py  = offy[k] + (float)(ki - 1 + ho);
            const float pxx = offx[k] + (float)(kj - 1 + p);

            const float y0f = floorf(py), x0f = floorf(pxx);
            const float ly = py - y0f,  lx = pxx - x0f;
            const float hy = 1.f - ly,  hx = 1.f - lx;
            const int y0 = (int)y0f, x0 = (int)x0f;

            const float wy0 = (y0 >= 0  && y0 < H_)     ? hy : 0.f;
            const float wy1 = (y0 >= -1 && y0 < H_ - 1) ? ly : 0.f;
            const int ry0 = min(max(y0, 0), H_ - 1);
            const int ry1 = min(max(y0 + 1, 0), H_ - 1);

            float wa, wb;                     // paired-x weights w/ boundary fold
            if (x0 >= 0 && x0 < W_) { wa = hx; wb = (x0 < W_ - 1) ? lx : 0.f; }
            else if (x0 == -1)      { wa = lx; wb = 0.f; }
            else                    { wa = 0.f; wb = 0.f; }
            const int bx = min(max(x0, 0), W_ - 1);

            const float u0 = wy0 * wa, u1 = wy0 * wb;
            const float u2 = wy1 * wa, u3 = wy1 * wb;

            const float2* p0 = xb2 + ry0 * W_ + bx;
            const float2* p1 = xb2 + ry1 * W_ + bx;
            float* vt = vtile + s * VT_FLOATS + p;
            #pragma unroll 8
            for (int c = 0; c < C_; c++) {
                const float2 a = __ldg(p0 + c * HW_);
                const float2 b = __ldg(p1 + c * HW_);
                vt[c * W_] = u0 * a.x + u1 * a.y + u2 * b.x + u3 * b.y;
            }

            BARRIVE(1 + s);                  // stage full
        }
    } else {
        // ================= CONSUMER (warps 0-3) =================
        const int pxq = tid & 31;            // pixel quad
        const int og  = tid >> 5;            // o-group (0..3), 16 o each

        unsigned long long acc[32];
        #pragma unroll
        for (int i = 0; i < 32; i++) acc[i] = 0ULL;

        for (int k = 0; k < KK; k++) {
            const int s = k & 1;
            BSYNC(1 + s);                    // wait stage full

            const float4*     vt = (const float4*)(vtile + s * VT_FLOATS);
            const ulonglong2* wt = (const ulonglong2*)(wslab + s * WS_FLOATS);
            #pragma unroll 2
            for (int c = 0; c < C_; c++) {
                const float4 v4 = vt[c * 32 + pxq];
                const ulonglong2* wr = wt + c * 16 + og * 4;
                const ulonglong2 wA = wr[0], wB = wr[1], wC = wr[2], wD = wr[3];

                unsigned long long vv0, vv1, vv2, vv3;
                PACK2(vv0, v4.x); PACK2(vv1, v4.y);
                PACK2(vv2, v4.z); PACK2(vv3, v4.w);

                FMA2(acc[0],  wA.x, vv0); FMA2(acc[1],  wA.y, vv0);
                FMA2(acc[2],  wB.x, vv0); FMA2(acc[3],  wB.y, vv0);
                FMA2(acc[4],  wC.x, vv0); FMA2(acc[5],  wC.y, vv0);
                FMA2(acc[6],  wD.x, vv0); FMA2(acc[7],  wD.y, vv0);

                FMA2(acc[8],  wA.x, vv1); FMA2(acc[9],  wA.y, vv1);
                FMA2(acc[10], wB.x, vv1); FMA2(acc[11], wB.y, vv1);
                FMA2(acc[12], wC.x, vv1); FMA2(acc[13], wC.y, vv1);
                FMA2(acc[14], wD.x, vv1); FMA2(acc[15], wD.y, vv1);

                FMA2(acc[16], wA.x, vv2); FMA2(acc[17], wA.y, vv2);
                FMA2(acc[18], wB.x, vv2); FMA2(acc[19], wB.y, vv2);
                FMA2(acc[20], wC.x, vv2); FMA2(acc[21], wC.y, vv2);
                FMA2(acc[22], wD.x, vv2); FMA2(acc[23], wD.y, vv2);

                FMA2(acc[24], wA.x, vv3); FMA2(acc[25], wA.y, vv3);
                FMA2(acc[26], wB.x, vv3); FMA2(acc[27], wB.y, vv3);
                FMA2(acc[28], wC.x, vv3); FMA2(acc[29], wC.y, vv3);
                FMA2(acc[30], wD.x, vv3); FMA2(acc[31], wD.y, vv3);
            }

            BARRIVE(3 + s);                  // stage empty
        }

        // epilogue: unpack, add bias, vector stores (4 px contiguous per o)
        float* ob = out + (batch * O_) * HW_ + ho * W_ + pxq * 4;
        #pragma unroll
        for (int pr = 0; pr < 8; pr++) {
            const int o = og * 16 + 2 * pr;
            const float b0 = __ldg(bias + o);
            const float b1 = __ldg(bias + o + 1);
            unsigned int l0, h0, l1, h1, l2, h2, l3, h3;
            UNPK(l0, h0, acc[pr]);
            UNPK(l1, h1, acc[8 + pr]);
            UNPK(l2, h2, acc[16 + pr]);
            UNPK(l3, h3, acc[24 + pr]);
            float4 r0 = make_float4(__uint_as_float(l0) + b0, __uint_as_float(l1) + b0,
                                    __uint_as_float(l2) + b0, __uint_as_float(l3) + b0);
            float4 r1 = make_float4(__uint_as_float(h0) + b1, __uint_as_float(h1) + b1,
                                    __uint_as_float(h2) + b1, __uint_as_float(h3) + b1);
            *(float4*)(ob + o * HW_)       = r0;
            *(float4*)(ob + (o + 1) * HW_) = r1;
        }
    }
}

extern "C" void kernel_launch(void* const* d_in, const int* in_sizes, int n_in,
                              void* d_out, int out_size) {
    const float* x      = (const float*)d_in[0];
    const float* offset = (const float*)d_in[1];
    const float* weight = (const float*)d_in[2];
    const float* bias   = (const float*)d_in[3];
    float* out = (float*)d_out;

    cudaFuncSetAttribute(dconv_main,
                         cudaFuncAttributeMaxDynamicSharedMemorySize, SMEM_BYTES);

    prep_weights<<<(O_ * C_ * KK + 255) / 256, 256>>>(weight);
    prep_x2<<<(B_ * C_ * HW_ + 255) / 256, 256>>>(x);
    dconv_main<<<B_ * H_, 256, SMEM_BYTES>>>(offset, bias, out);
}